// round 13
// baseline (speedup 1.0000x reference)
#include <cuda_runtime.h>

static constexpr int BATCH = 8;
static constexpr int SEQ   = 16384;
static constexpr int CH    = 256;
static constexpr int TOPN  = 2048;
static constexpr int ROWS  = BATCH * SEQ;     // 131072
static constexpr int QUADS = ROWS / 4;        // 32768

static constexpr int K1_GRID    = 444;        // 148 SMs * 3 resident CTAs
static constexpr int K1_THREADS = 256;        // 8 warps
static constexpr int K1_WARPS_TOTAL = K1_GRID * (K1_THREADS / 32);  // 3552

__device__ float g_score[ROWS];
__device__ float g_psum[K1_GRID];
__device__ float g_psq[K1_GRID];
__device__ unsigned g_idx[BATCH * TOPN];
__device__ unsigned long long g_keys[ROWS];   // slow-path scratch (global)

// PDL primitives (sm_90+)
#define GRID_WAIT()    asm volatile("griddepcontrol.wait;" ::: "memory")
#define GRID_TRIGGER() asm volatile("griddepcontrol.launch_dependents;" ::: "memory")

// ---------------------------------------------------------------------------
// K1: persistent grid-stride. A warp covers 4 rows, 8 lanes per row
// (lane = 8*subrow + pos). 8 front-batched float4 streaming loads per thread;
// row reduce = 3-step shfl butterfly (4 rows simultaneously in one register).
// ---------------------------------------------------------------------------
__global__ __launch_bounds__(K1_THREADS, 3) void score_kernel(const float* __restrict__ x,
                                                              const float* __restrict__ w,
                                                              const float* __restrict__ bias) {
    const int warp   = threadIdx.x >> 5;
    const int lane   = threadIdx.x & 31;
    const int subrow = lane >> 3;
    const int pos    = lane & 7;
    const int gw     = blockIdx.x * (K1_THREADS / 32) + warp;

    const float4* wv = (const float4*)w;
    float4 W[8];
#pragma unroll
    for (int j = 0; j < 8; j++) W[j] = wv[pos + 8*j];
    const float bb = bias[0];

    float S = 0.f, Q = 0.f;

    for (int quad = gw; quad < QUADS; quad += K1_WARPS_TOTAL) {
        const size_t row = (size_t)quad * 4 + subrow;
        const float4* xb = (const float4*)(x + row * CH);

        float4 v[8];
#pragma unroll
        for (int j = 0; j < 8; j++) v[j] = __ldcs(xb + pos + 8*j);

        float d = 0.f;
#pragma unroll
        for (int j = 0; j < 8; j++)
            d += v[j].x*W[j].x + v[j].y*W[j].y + v[j].z*W[j].z + v[j].w*W[j].w;

        d += __shfl_xor_sync(0xffffffffu, d, 4);
        d += __shfl_xor_sync(0xffffffffu, d, 2);
        d += __shfl_xor_sync(0xffffffffu, d, 1);

        if (pos == 0) {
            float c = d + bb;
            __stcs(&g_score[row], c);
            S += c;
            Q += c * c;
        }
    }

#pragma unroll
    for (int off = 16; off > 0; off >>= 1) {
        S += __shfl_xor_sync(0xffffffffu, S, off);
        Q += __shfl_xor_sync(0xffffffffu, Q, off);
    }
    __shared__ float ws[K1_THREADS / 32], wq[K1_THREADS / 32];
    if (lane == 0) { ws[warp] = S; wq[warp] = Q; }
    __syncthreads();
    if (threadIdx.x < 32) {
        float s = (threadIdx.x < K1_THREADS / 32) ? ws[threadIdx.x] : 0.f;
        float q = (threadIdx.x < K1_THREADS / 32) ? wq[threadIdx.x] : 0.f;
#pragma unroll
        for (int off = 4; off > 0; off >>= 1) {
            s += __shfl_xor_sync(0xffffffffu, s, off);
            q += __shfl_xor_sync(0xffffffffu, q, off);
        }
        if (threadIdx.x == 0) { g_psum[blockIdx.x] = s; g_psq[blockIdx.x] = q; }
    }
    GRID_TRIGGER();   // stores above are visible to dependents after their wait
}

// ---------------------------------------------------------------------------
// K2: one CTA per batch. Fast path: ReLU zeros (normalized <= 0) are first
// in stable ascending argsort, in index order -> stream compaction of the
// first TOPN qualifying indices. Slow path (practically unreachable):
// iterative global argmin on 46-bit stable keys in global scratch.
// ---------------------------------------------------------------------------
__global__ __launch_bounds__(1024) void select_kernel(const float* __restrict__ gamma,
                                                      const float* __restrict__ beta) {
    __shared__ float red1[512], red2[512];
    __shared__ unsigned warpsum[32];
    __shared__ unsigned warpexcl[32];
    __shared__ unsigned total_s;

    const int tid  = threadIdx.x;
    const int lane = tid & 31;
    const int warp = tid >> 5;
    const int b    = blockIdx.x;

    const float gam = gamma[0];      // independent inputs: load before wait
    const float bet = beta[0];
    GRID_WAIT();                     // g_psum/g_psq/g_score now visible

    if (tid < 512) {
        float S = (tid < K1_GRID) ? g_psum[tid] : 0.f;
        float Q = (tid < K1_GRID) ? g_psq[tid]  : 0.f;
        red1[tid] = S; red2[tid] = Q;
    }
    __syncthreads();
    for (int off = 256; off > 0; off >>= 1) {
        if (tid < off) { red1[tid] += red1[tid + off]; red2[tid] += red2[tid + off]; }
        __syncthreads();
    }
    float mean = red1[0] / (float)ROWS;
    float var  = red2[0] / (float)ROWS - mean * mean;
    if (var < 0.f) var = 0.f;
    float scale = rsqrtf(var + 1e-5f) * gam;
    float shift = bet - mean * scale;

    const float* sc = g_score + (size_t)b * SEQ;
    const float4* p4 = (const float4*)(sc + tid * 16);
    unsigned mask16 = 0;
#pragma unroll
    for (int j = 0; j < 4; j++) {
        float4 v = p4[j];
        if (fmaf(v.x, scale, shift) <= 0.f) mask16 |= 1u << (4*j + 0);
        if (fmaf(v.y, scale, shift) <= 0.f) mask16 |= 1u << (4*j + 1);
        if (fmaf(v.z, scale, shift) <= 0.f) mask16 |= 1u << (4*j + 2);
        if (fmaf(v.w, scale, shift) <= 0.f) mask16 |= 1u << (4*j + 3);
    }
    unsigned c = (unsigned)__popc(mask16);

    unsigned incl = c;
#pragma unroll
    for (int off = 1; off < 32; off <<= 1) {
        unsigned n = __shfl_up_sync(0xffffffffu, incl, off);
        if (lane >= off) incl += n;
    }
    if (lane == 31) warpsum[warp] = incl;
    __syncthreads();
    if (tid < 32) {
        unsigned wv = warpsum[tid];
        unsigned wincl = wv;
#pragma unroll
        for (int off = 1; off < 32; off <<= 1) {
            unsigned n = __shfl_up_sync(0xffffffffu, wincl, off);
            if (tid >= off) wincl += n;
        }
        warpexcl[tid] = wincl - wv;
        if (tid == 31) total_s = wincl;
    }
    __syncthreads();
    unsigned T = total_s;

    if (T >= (unsigned)TOPN) {
        unsigned r = warpexcl[warp] + (incl - c);
        if (r < (unsigned)TOPN) {
            unsigned base_i = (unsigned)tid * 16u;
#pragma unroll
            for (int j = 0; j < 16; j++) {
                if (mask16 & (1u << j)) {
                    if (r < (unsigned)TOPN) g_idx[b * TOPN + r] = base_i + j;
                    r++;
                }
            }
        }
        GRID_TRIGGER();
        return;
    }

    // ===== slow path: iterative global argmin (correctness-only) =====
    unsigned long long* kb = g_keys + (size_t)b * SEQ;
    for (int i = tid; i < SEQ; i += 1024) {
        float r = fmaxf(0.f, fmaf(sc[i], scale, shift));
        kb[i] = ((unsigned long long)__float_as_uint(r) << 14) | (unsigned)i;
    }
    __syncthreads();
    __shared__ unsigned long long mv[1024];
    __shared__ int mp[1024];
    for (int r = 0; r < TOPN; r++) {
        unsigned long long best = ~0ULL; int bp = 0;
        for (int i = tid; i < SEQ; i += 1024) {
            unsigned long long k = kb[i];
            if (k < best) { best = k; bp = i; }
        }
        mv[tid] = best; mp[tid] = bp;
        __syncthreads();
        for (int off = 512; off > 0; off >>= 1) {
            if (tid < off && mv[tid + off] < mv[tid]) {
                mv[tid] = mv[tid + off]; mp[tid] = mp[tid + off];
            }
            __syncthreads();
        }
        if (tid == 0) {
            g_idx[b * TOPN + r] = (unsigned)(mv[0] & 0x3fffu);
            kb[mp[0]] = ~0ULL;
        }
        __syncthreads();
    }
    GRID_TRIGGER();
}

// ---------------------------------------------------------------------------
// K3: gather rows: out[b, r, :] = x_select[b, idx[b,r], :]
// 512 threads / 64 rows per block. Row indices staged in smem; 8 threads per
// row, each moving 8 front-batched float4s (MLP=8).
// ---------------------------------------------------------------------------
__global__ __launch_bounds__(512) void gather_kernel(const float* __restrict__ xs,
                                                     float* __restrict__ out) {
    __shared__ unsigned sidx[64];
    const int t = threadIdx.x;
    const int row0 = blockIdx.x * 64;
    GRID_WAIT();                     // g_idx now visible
    if (t < 64) sidx[t] = g_idx[row0 + t];
    __syncthreads();

    const int lrow = t >> 3;                     // 0..63
    const int pos  = t & 7;                      // 0..7
    const int rid  = row0 + lrow;
    const int b    = rid >> 11;                  // TOPN == 2048
    const unsigned idx = sidx[lrow];

    const float4* src = (const float4*)(xs + ((size_t)b * SEQ + idx) * CH);
    float4* dst = (float4*)(out + (size_t)rid * CH);

    float4 v[8];
#pragma unroll
    for (int j = 0; j < 8; j++) v[j] = __ldcs(src + pos + 8*j);
#pragma unroll
    for (int j = 0; j < 8; j++) __stcs(dst + pos + 8*j, v[j]);
}

// ---------------------------------------------------------------------------
static inline void launch_pdl(void* fn, dim3 grid, dim3 block,
                              void** args) {
    cudaLaunchConfig_t cfg = {};
    cfg.gridDim  = grid;
    cfg.blockDim = block;
    cfg.dynamicSmemBytes = 0;
    cfg.stream = 0;
    cudaLaunchAttribute attr[1];
    attr[0].id = cudaLaunchAttributeProgrammaticStreamSerialization;
    attr[0].val.programmaticStreamSerializationAllowed = 1;
    cfg.attrs = attr;
    cfg.numAttrs = 1;
    cudaLaunchKernelExC(&cfg, fn, args);
}

extern "C" void kernel_launch(void* const* d_in, const int* in_sizes, int n_in,
                              void* d_out, int out_size) {
    const float* x_in  = (const float*)d_in[0];
    const float* x_sel = (const float*)d_in[1];
    const float* w     = (const float*)d_in[2];
    const float* bias  = (const float*)d_in[3];
    const float* gamma = (const float*)d_in[4];
    const float* beta  = (const float*)d_in[5];
    float* out = (float*)d_out;

    score_kernel<<<K1_GRID, K1_THREADS>>>(x_in, w, bias);

    {   // select: PDL-dependent on score_kernel
        void* args[] = { (void*)&gamma, (void*)&beta };
        launch_pdl((void*)select_kernel, dim3(BATCH), dim3(1024), args);
    }
    {   // gather: PDL-dependent on select_kernel
        void* args[] = { (void*)&x_sel, (void*)&out };
        launch_pdl((void*)gather_kernel, dim3((BATCH * TOPN) / 64), dim3(512), args);
    }
}

// round 14
// speedup vs baseline: 1.1041x; 1.1041x over previous
#include <cuda_runtime.h>

static constexpr int BATCH = 8;
static constexpr int SEQ   = 16384;
static constexpr int CH    = 256;
static constexpr int TOPN  = 2048;
static constexpr int ROWS  = BATCH * SEQ;     // 131072
static constexpr int QUADS = ROWS / 4;        // 32768

static constexpr int K1_GRID    = 444;        // 148 SMs * 3 resident CTAs
static constexpr int K1_THREADS = 256;        // 8 warps
static constexpr int K1_WARPS_TOTAL = K1_GRID * (K1_THREADS / 32);  // 3552

static constexpr int SLICES     = 32;                 // gather CTAs per batch
static constexpr int SLICE_ROWS = TOPN / SLICES;      // 64
static constexpr int G_THREADS  = 512;

__device__ float g_score[ROWS];
__device__ float g_psum[K1_GRID];
__device__ float g_psq[K1_GRID];
__device__ unsigned g_idx[BATCH * TOPN];
__device__ unsigned long long g_keys[ROWS];   // slow-path scratch (global)
__device__ unsigned g_flag[BATCH] = {};       // select-done flags (self-resetting)
__device__ unsigned g_fin[BATCH]  = {};       // gather-slice completion counters

// ---------------------------------------------------------------------------
// K1: persistent grid-stride. A warp covers 4 rows, 8 lanes per row
// (lane = 8*subrow + pos). 8 front-batched float4 streaming loads per thread;
// row reduce = 3-step shfl butterfly (4 rows simultaneously in one register).
// ---------------------------------------------------------------------------
__global__ __launch_bounds__(K1_THREADS, 3) void score_kernel(const float* __restrict__ x,
                                                              const float* __restrict__ w,
                                                              const float* __restrict__ bias) {
    const int warp   = threadIdx.x >> 5;
    const int lane   = threadIdx.x & 31;
    const int subrow = lane >> 3;
    const int pos    = lane & 7;
    const int gw     = blockIdx.x * (K1_THREADS / 32) + warp;

    const float4* wv = (const float4*)w;
    float4 W[8];
#pragma unroll
    for (int j = 0; j < 8; j++) W[j] = wv[pos + 8*j];
    const float bb = bias[0];

    float S = 0.f, Q = 0.f;

    for (int quad = gw; quad < QUADS; quad += K1_WARPS_TOTAL) {
        const size_t row = (size_t)quad * 4 + subrow;
        const float4* xb = (const float4*)(x + row * CH);

        float4 v[8];
#pragma unroll
        for (int j = 0; j < 8; j++) v[j] = __ldcs(xb + pos + 8*j);

        float d = 0.f;
#pragma unroll
        for (int j = 0; j < 8; j++)
            d += v[j].x*W[j].x + v[j].y*W[j].y + v[j].z*W[j].z + v[j].w*W[j].w;

        d += __shfl_xor_sync(0xffffffffu, d, 4);
        d += __shfl_xor_sync(0xffffffffu, d, 2);
        d += __shfl_xor_sync(0xffffffffu, d, 1);

        if (pos == 0) {
            float c = d + bb;
            __stcs(&g_score[row], c);
            S += c;
            Q += c * c;
        }
    }

#pragma unroll
    for (int off = 16; off > 0; off >>= 1) {
        S += __shfl_xor_sync(0xffffffffu, S, off);
        Q += __shfl_xor_sync(0xffffffffu, Q, off);
    }
    __shared__ float ws[K1_THREADS / 32], wq[K1_THREADS / 32];
    if (lane == 0) { ws[warp] = S; wq[warp] = Q; }
    __syncthreads();
    if (threadIdx.x < 32) {
        float s = (threadIdx.x < K1_THREADS / 32) ? ws[threadIdx.x] : 0.f;
        float q = (threadIdx.x < K1_THREADS / 32) ? wq[threadIdx.x] : 0.f;
#pragma unroll
        for (int off = 4; off > 0; off >>= 1) {
            s += __shfl_xor_sync(0xffffffffu, s, off);
            q += __shfl_xor_sync(0xffffffffu, q, off);
        }
        if (threadIdx.x == 0) { g_psum[blockIdx.x] = s; g_psq[blockIdx.x] = q; }
    }
}

// ---------------------------------------------------------------------------
// K2 (fused select + gather), 264 CTAs of 512 threads:
//   blocks 0..7      : select for batch b = blockIdx. Mean/var from partials,
//                      stable compaction of normalized <= 0 (relu zeros lead a
//                      stable ascending argsort in index order), write g_idx,
//                      fence, publish flag. Slow path (T < TOPN, practically
//                      unreachable): iterative argmin on stable keys.
//   blocks 8..263    : gather slice (64 rows). Spin briefly on the batch flag
//                      (select is ~1.3us), stage indices to smem, gather with
//                      8 front-batched float4 per thread.
// Flags/counters self-reset (last slice CTA per batch) for graph replays.
// All 264 CTAs fit in wave 1 -> no spin deadlock.
// ---------------------------------------------------------------------------
__global__ __launch_bounds__(G_THREADS) void select_gather_kernel(
        const float* __restrict__ xs,
        const float* __restrict__ gamma,
        const float* __restrict__ beta,
        float* __restrict__ out) {
    const int tid  = threadIdx.x;
    const int lane = tid & 31;
    const int warp = tid >> 5;

    if (blockIdx.x < BATCH) {
        // ================= select role =================
        const int b = blockIdx.x;
        __shared__ float red1[G_THREADS], red2[G_THREADS];
        __shared__ unsigned warpsum[16], warpexcl[16];
        __shared__ unsigned total_s;

        {
            float S = (tid < K1_GRID) ? g_psum[tid] : 0.f;
            float Q = (tid < K1_GRID) ? g_psq[tid]  : 0.f;
            red1[tid] = S; red2[tid] = Q;
        }
        __syncthreads();
        for (int off = 256; off > 0; off >>= 1) {
            if (tid < off) { red1[tid] += red1[tid + off]; red2[tid] += red2[tid + off]; }
            __syncthreads();
        }
        const float mean = red1[0] / (float)ROWS;
        float var  = red2[0] / (float)ROWS - mean * mean;
        if (var < 0.f) var = 0.f;
        const float scale = rsqrtf(var + 1e-5f) * gamma[0];
        const float shift = beta[0] - mean * scale;

        // compaction scan: 32 elements per thread
        const float* sc = g_score + (size_t)b * SEQ;
        const int base = tid * 32;
        const float4* p4 = (const float4*)(sc + base);
        unsigned m0 = 0;
#pragma unroll
        for (int j = 0; j < 8; j++) {
            float4 v = p4[j];
            if (fmaf(v.x, scale, shift) <= 0.f) m0 |= 1u << (4*j + 0);
            if (fmaf(v.y, scale, shift) <= 0.f) m0 |= 1u << (4*j + 1);
            if (fmaf(v.z, scale, shift) <= 0.f) m0 |= 1u << (4*j + 2);
            if (fmaf(v.w, scale, shift) <= 0.f) m0 |= 1u << (4*j + 3);
        }
        const unsigned c = (unsigned)__popc(m0);

        unsigned incl = c;
#pragma unroll
        for (int off = 1; off < 32; off <<= 1) {
            unsigned n = __shfl_up_sync(0xffffffffu, incl, off);
            if (lane >= off) incl += n;
        }
        if (lane == 31) warpsum[warp] = incl;
        __syncthreads();
        if (tid < 16) {
            unsigned wv = warpsum[tid];
            unsigned e = 0;
            for (int j = 0; j < 16; j++) if (j < tid) e += warpsum[j];
            warpexcl[tid] = e;
            if (tid == 15) total_s = e + wv;
        }
        __syncthreads();
        const unsigned T = total_s;

        if (T >= (unsigned)TOPN) {
            unsigned r = warpexcl[warp] + (incl - c);
            if (r < (unsigned)TOPN) {
#pragma unroll
                for (int j = 0; j < 32; j++) {
                    if (m0 & (1u << j)) {
                        if (r < (unsigned)TOPN) g_idx[b * TOPN + r] = (unsigned)(base + j);
                        r++;
                    }
                }
            }
        } else {
            // ===== slow path: iterative global argmin (correctness-only) =====
            unsigned long long* kb = g_keys + (size_t)b * SEQ;
            for (int i = tid; i < SEQ; i += G_THREADS) {
                float r = fmaxf(0.f, fmaf(sc[i], scale, shift));
                kb[i] = ((unsigned long long)__float_as_uint(r) << 14) | (unsigned)i;
            }
            __syncthreads();
            __shared__ unsigned long long mv[G_THREADS];
            __shared__ int mp[G_THREADS];
            for (int r = 0; r < TOPN; r++) {
                unsigned long long best = ~0ULL; int bp = 0;
                for (int i = tid; i < SEQ; i += G_THREADS) {
                    unsigned long long k = kb[i];
                    if (k < best) { best = k; bp = i; }
                }
                mv[tid] = best; mp[tid] = bp;
                __syncthreads();
                for (int off = 256; off > 0; off >>= 1) {
                    if (tid < off && mv[tid + off] < mv[tid]) {
                        mv[tid] = mv[tid + off]; mp[tid] = mp[tid + off];
                    }
                    __syncthreads();
                }
                if (tid == 0) {
                    g_idx[b * TOPN + r] = (unsigned)(mv[0] & 0x3fffu);
                    kb[mp[0]] = ~0ULL;
                }
                __syncthreads();
            }
        }

        // publish
        __syncthreads();
        __threadfence();
        if (tid == 0) atomicExch(&g_flag[b], 1u);
        return;
    }

    // ================= gather role =================
    const int gblk = blockIdx.x - BATCH;
    const int row0 = gblk * SLICE_ROWS;          // first output row
    const int b    = row0 >> 11;                 // TOPN == 2048

    __shared__ unsigned sidx[SLICE_ROWS];

    if (tid == 0) {
        while (atomicAdd(&g_flag[b], 0u) == 0u) __nanosleep(64);
    }
    __syncthreads();
    __threadfence();

    if (tid < SLICE_ROWS) sidx[tid] = g_idx[row0 + tid];
    __syncthreads();

    // indices staged; last slice CTA of this batch resets flag + counter
    if (tid == 0) {
        unsigned d = atomicAdd(&g_fin[b], 1u);
        if (d == (unsigned)(SLICES - 1)) {
            atomicExch(&g_flag[b], 0u);
            atomicExch(&g_fin[b], 0u);
        }
    }

    const int lrow = tid >> 3;                   // 0..63
    const int pos  = tid & 7;                    // 0..7
    const unsigned idx = sidx[lrow];
    const float4* src = (const float4*)(xs + ((size_t)b * SEQ + idx) * CH);
    float4* dst = (float4*)(out + (size_t)(row0 + lrow) * CH);

    float4 v[8];
#pragma unroll
    for (int j = 0; j < 8; j++) v[j] = __ldcs(src + pos + 8*j);
#pragma unroll
    for (int j = 0; j < 8; j++) __stcs(dst + pos + 8*j, v[j]);
}

// ---------------------------------------------------------------------------
extern "C" void kernel_launch(void* const* d_in, const int* in_sizes, int n_in,
                              void* d_out, int out_size) {
    const float* x_in  = (const float*)d_in[0];
    const float* x_sel = (const float*)d_in[1];
    const float* w     = (const float*)d_in[2];
    const float* bias  = (const float*)d_in[3];
    const float* gamma = (const float*)d_in[4];
    const float* beta  = (const float*)d_in[5];
    float* out = (float*)d_out;

    score_kernel<<<K1_GRID, K1_THREADS>>>(x_in, w, bias);
    select_gather_kernel<<<BATCH + BATCH * SLICES, G_THREADS>>>(x_sel, gamma, beta, out);
}

// round 15
// speedup vs baseline: 1.2403x; 1.1233x over previous
#include <cuda_runtime.h>

static constexpr int BATCH = 8;
static constexpr int SEQ   = 16384;
static constexpr int CH    = 256;
static constexpr int TOPN  = 2048;
static constexpr int ROWS  = BATCH * SEQ;     // 131072
static constexpr int QUADS = ROWS / 4;        // 32768

static constexpr int K1_GRID    = 444;        // 148 SMs * 3 resident CTAs
static constexpr int K1_THREADS = 256;        // 8 warps
static constexpr int K1_WARPS_TOTAL = K1_GRID * (K1_THREADS / 32);  // 3552

__device__ float g_score[ROWS];
__device__ float g_psum[K1_GRID];
__device__ float g_psq[K1_GRID];
__device__ unsigned g_idx[BATCH * TOPN];
__device__ unsigned long long g_keys[ROWS];   // slow-path scratch (global)

// ---------------------------------------------------------------------------
// K1: persistent grid-stride. A warp covers 4 rows, 8 lanes per row
// (lane = 8*subrow + pos). 8 front-batched float4 streaming loads per thread;
// row reduce = 3-step shfl butterfly (4 rows simultaneously in one register).
// ---------------------------------------------------------------------------
__global__ __launch_bounds__(K1_THREADS, 3) void score_kernel(const float* __restrict__ x,
                                                              const float* __restrict__ w,
                                                              const float* __restrict__ bias) {
    const int warp   = threadIdx.x >> 5;
    const int lane   = threadIdx.x & 31;
    const int subrow = lane >> 3;
    const int pos    = lane & 7;
    const int gw     = blockIdx.x * (K1_THREADS / 32) + warp;

    const float4* wv = (const float4*)w;
    float4 W[8];
#pragma unroll
    for (int j = 0; j < 8; j++) W[j] = wv[pos + 8*j];
    const float bb = bias[0];

    float S = 0.f, Q = 0.f;

    for (int quad = gw; quad < QUADS; quad += K1_WARPS_TOTAL) {
        const size_t row = (size_t)quad * 4 + subrow;
        const float4* xb = (const float4*)(x + row * CH);

        float4 v[8];
#pragma unroll
        for (int j = 0; j < 8; j++) v[j] = __ldcs(xb + pos + 8*j);

        float d = 0.f;
#pragma unroll
        for (int j = 0; j < 8; j++)
            d += v[j].x*W[j].x + v[j].y*W[j].y + v[j].z*W[j].z + v[j].w*W[j].w;

        d += __shfl_xor_sync(0xffffffffu, d, 4);
        d += __shfl_xor_sync(0xffffffffu, d, 2);
        d += __shfl_xor_sync(0xffffffffu, d, 1);

        if (pos == 0) {
            float c = d + bb;
            __stcs(&g_score[row], c);
            S += c;
            Q += c * c;
        }
    }

#pragma unroll
    for (int off = 16; off > 0; off >>= 1) {
        S += __shfl_xor_sync(0xffffffffu, S, off);
        Q += __shfl_xor_sync(0xffffffffu, Q, off);
    }
    __shared__ float ws[K1_THREADS / 32], wq[K1_THREADS / 32];
    if (lane == 0) { ws[warp] = S; wq[warp] = Q; }
    __syncthreads();
    if (threadIdx.x < 32) {
        float s = (threadIdx.x < K1_THREADS / 32) ? ws[threadIdx.x] : 0.f;
        float q = (threadIdx.x < K1_THREADS / 32) ? wq[threadIdx.x] : 0.f;
#pragma unroll
        for (int off = 4; off > 0; off >>= 1) {
            s += __shfl_xor_sync(0xffffffffu, s, off);
            q += __shfl_xor_sync(0xffffffffu, q, off);
        }
        if (threadIdx.x == 0) { g_psum[blockIdx.x] = s; g_psq[blockIdx.x] = q; }
    }
}

// ---------------------------------------------------------------------------
// K2: one CTA per batch. Fast path: ReLU zeros (normalized <= 0) are first
// in stable ascending argsort, in index order -> stream compaction of the
// first TOPN qualifying indices. Slow path (practically unreachable):
// iterative global argmin on 46-bit stable keys in global scratch.
// ---------------------------------------------------------------------------
__global__ __launch_bounds__(1024) void select_kernel(const float* __restrict__ gamma,
                                                      const float* __restrict__ beta) {
    __shared__ float red1[512], red2[512];
    __shared__ unsigned warpsum[32];
    __shared__ unsigned warpexcl[32];
    __shared__ unsigned total_s;

    const int tid  = threadIdx.x;
    const int lane = tid & 31;
    const int warp = tid >> 5;
    const int b    = blockIdx.x;

    if (tid < 512) {
        float S = (tid < K1_GRID) ? g_psum[tid] : 0.f;
        float Q = (tid < K1_GRID) ? g_psq[tid]  : 0.f;
        red1[tid] = S; red2[tid] = Q;
    }
    __syncthreads();
    for (int off = 256; off > 0; off >>= 1) {
        if (tid < off) { red1[tid] += red1[tid + off]; red2[tid] += red2[tid + off]; }
        __syncthreads();
    }
    float mean = red1[0] / (float)ROWS;
    float var  = red2[0] / (float)ROWS - mean * mean;
    if (var < 0.f) var = 0.f;
    float scale = rsqrtf(var + 1e-5f) * gamma[0];
    float shift = beta[0] - mean * scale;

    const float* sc = g_score + (size_t)b * SEQ;
    const float4* p4 = (const float4*)(sc + tid * 16);
    unsigned mask16 = 0;
#pragma unroll
    for (int j = 0; j < 4; j++) {
        float4 v = p4[j];
        if (fmaf(v.x, scale, shift) <= 0.f) mask16 |= 1u << (4*j + 0);
        if (fmaf(v.y, scale, shift) <= 0.f) mask16 |= 1u << (4*j + 1);
        if (fmaf(v.z, scale, shift) <= 0.f) mask16 |= 1u << (4*j + 2);
        if (fmaf(v.w, scale, shift) <= 0.f) mask16 |= 1u << (4*j + 3);
    }
    unsigned c = (unsigned)__popc(mask16);

    unsigned incl = c;
#pragma unroll
    for (int off = 1; off < 32; off <<= 1) {
        unsigned n = __shfl_up_sync(0xffffffffu, incl, off);
        if (lane >= off) incl += n;
    }
    if (lane == 31) warpsum[warp] = incl;
    __syncthreads();
    if (tid < 32) {
        unsigned wv = warpsum[tid];
        unsigned wincl = wv;
#pragma unroll
        for (int off = 1; off < 32; off <<= 1) {
            unsigned n = __shfl_up_sync(0xffffffffu, wincl, off);
            if (tid >= off) wincl += n;
        }
        warpexcl[tid] = wincl - wv;
        if (tid == 31) total_s = wincl;
    }
    __syncthreads();
    unsigned T = total_s;

    if (T >= (unsigned)TOPN) {
        unsigned r = warpexcl[warp] + (incl - c);
        if (r < (unsigned)TOPN) {
            unsigned base_i = (unsigned)tid * 16u;
#pragma unroll
            for (int j = 0; j < 16; j++) {
                if (mask16 & (1u << j)) {
                    if (r < (unsigned)TOPN) g_idx[b * TOPN + r] = base_i + j;
                    r++;
                }
            }
        }
        return;
    }

    // ===== slow path: iterative global argmin (correctness-only) =====
    unsigned long long* kb = g_keys + (size_t)b * SEQ;
    for (int i = tid; i < SEQ; i += 1024) {
        float r = fmaxf(0.f, fmaf(sc[i], scale, shift));
        kb[i] = ((unsigned long long)__float_as_uint(r) << 14) | (unsigned)i;
    }
    __syncthreads();
    __shared__ unsigned long long mv[1024];
    __shared__ int mp[1024];
    for (int r = 0; r < TOPN; r++) {
        unsigned long long best = ~0ULL; int bp = 0;
        for (int i = tid; i < SEQ; i += 1024) {
            unsigned long long k = kb[i];
            if (k < best) { best = k; bp = i; }
        }
        mv[tid] = best; mp[tid] = bp;
        __syncthreads();
        for (int off = 512; off > 0; off >>= 1) {
            if (tid < off && mv[tid + off] < mv[tid]) {
                mv[tid] = mv[tid + off]; mp[tid] = mp[tid + off];
            }
            __syncthreads();
        }
        if (tid == 0) {
            g_idx[b * TOPN + r] = (unsigned)(mv[0] & 0x3fffu);
            kb[mp[0]] = ~0ULL;
        }
        __syncthreads();
    }
}

// ---------------------------------------------------------------------------
// K3: gather rows: out[b, r, :] = x_select[b, idx[b,r], :]
// 512 CTAs x 128 threads: 16 rows/CTA, 8 threads/row, 8 front-batched float4
// per thread. ~3.5 CTAs/SM -> enough in-flight lines (BW x latency) without
// any smem staging / barrier in the dependent chain. Row index via __ldg
// (64 B per CTA, broadcast within each 8-thread group).
// ---------------------------------------------------------------------------
__global__ __launch_bounds__(128) void gather_kernel(const float* __restrict__ xs,
                                                     float* __restrict__ out) {
    const int t    = threadIdx.x;
    const int lrow = t >> 3;                     // 0..15
    const int pos  = t & 7;                      // 0..7
    const int rid  = blockIdx.x * 16 + lrow;     // 0 .. BATCH*TOPN-1
    const int b    = rid >> 11;                  // TOPN == 2048

    const unsigned idx = __ldg(&g_idx[rid]);
    const float4* src = (const float4*)(xs + ((size_t)b * SEQ + idx) * CH);
    float4* dst = (float4*)(out + (size_t)rid * CH);

    float4 v[8];
#pragma unroll
    for (int j = 0; j < 8; j++) v[j] = __ldcs(src + pos + 8*j);
#pragma unroll
    for (int j = 0; j < 8; j++) __stcs(dst + pos + 8*j, v[j]);
}

// ---------------------------------------------------------------------------
extern "C" void kernel_launch(void* const* d_in, const int* in_sizes, int n_in,
                              void* d_out, int out_size) {
    const float* x_in  = (const float*)d_in[0];
    const float* x_sel = (const float*)d_in[1];
    const float* w     = (const float*)d_in[2];
    const float* bias  = (const float*)d_in[3];
    const float* gamma = (const float*)d_in[4];
    const float* beta  = (const float*)d_in[5];
    float* out = (float*)d_out;

    score_kernel<<<K1_GRID, K1_THREADS>>>(x_in, w, bias);
    select_kernel<<<BATCH, 1024>>>(gamma, beta);
    gather_kernel<<<(BATCH * TOPN) / 16, 128>>>(x_sel, out);
}